// round 2
// baseline (speedup 1.0000x reference)
#include <cuda_runtime.h>
#include <cuda_bf16.h>
#include <cstdint>

#define ND 50000
#define ED 800000
#define DD 128

// ---------------- scratch (device globals; no allocation allowed) ----------------
__device__ float g_deg[ND];
__device__ float g_dinv[ND];
__device__ int   g_off[ND + 1];
__device__ int   g_cur[ND];
__device__ int   g_csr_src[ED];
__device__ float g_csr_norm[ED];
__device__ float g_h[ND * DD];     // X @ W
__device__ float g_t[ND * DD];     // pre-BN conv output
__device__ float g_stats[2 * DD];  // col sums / sumsq
__device__ float g_scale[DD];
__device__ float g_shift[DD];

// ---------------- f32x2 helpers ----------------
__device__ __forceinline__ unsigned long long ffma2(unsigned long long a,
                                                    unsigned long long b,
                                                    unsigned long long c) {
    unsigned long long d;
    asm("fma.rn.f32x2 %0, %1, %2, %3;" : "=l"(d) : "l"(a), "l"(b), "l"(c));
    return d;
}
__device__ __forceinline__ void unpack2(unsigned long long v, float& lo, float& hi) {
    asm("mov.b64 {%0, %1}, %2;" : "=f"(lo), "=f"(hi) : "l"(v));
}

// ---------------- init: deg=1, stats=0 ----------------
__global__ void k_init(int n) {
    int i = blockIdx.x * blockDim.x + threadIdx.x;
    if (i < n) g_deg[i] = 1.0f;
    if (i < 2 * DD) g_stats[i] = 0.0f;
}

__global__ void k_degree(const int* __restrict__ dst, int e) {
    int i = blockIdx.x * blockDim.x + threadIdx.x;
    if (i < e) atomicAdd(&g_deg[dst[i]], 1.0f);
}

// ---------------- single-block scan: offsets, cursors, dinv ----------------
__global__ __launch_bounds__(1024) void k_scan(int n) {
    __shared__ int part[1024];
    int tid = threadIdx.x;
    int chunk = (n + 1023) >> 10;
    int lo = tid * chunk, hi = min(lo + chunk, n);
    int s = 0;
    for (int i = lo; i < hi; i++) s += (int)(g_deg[i] - 0.5f);
    part[tid] = s;
    __syncthreads();
    // Hillis-Steele inclusive scan
    for (int off = 1; off < 1024; off <<= 1) {
        int v = (tid >= off) ? part[tid - off] : 0;
        __syncthreads();
        part[tid] += v;
        __syncthreads();
    }
    int run = part[tid] - s;  // exclusive base
    for (int i = lo; i < hi; i++) {
        g_off[i] = run;
        g_cur[i] = run;
        g_dinv[i] = rsqrtf(g_deg[i]);
        run += (int)(g_deg[i] - 0.5f);
    }
    if (tid == 1023) g_off[n] = part[1023];
}

// ---------------- fill CSR (counting sort by dst) ----------------
__global__ void k_fill(const int* __restrict__ src, const int* __restrict__ dst, int e) {
    int i = blockIdx.x * blockDim.x + threadIdx.x;
    if (i >= e) return;
    int s = src[i], d = dst[i];
    int pos = atomicAdd(&g_cur[d], 1);
    g_csr_src[pos] = s;
    g_csr_norm[pos] = g_dinv[s] * g_dinv[d];
}

// ---------------- GEMM: H = act(X) @ W via packed f32x2 ----------------
// 256 threads, 64 rows/block, K tiled by 32. X values duplicated into float2
// in smem so the inner loop is LDS.64 broadcast + FFMA2 (full-rate fp32).
// Optional fused BN+ReLU on the X load (scale/shift per column).
__global__ __launch_bounds__(256) void k_gemm(const float* __restrict__ X,
                                              const float* __restrict__ W,
                                              float* __restrict__ H, int nrows,
                                              const float* __restrict__ scale,
                                              const float* __restrict__ shift) {
    __shared__ float sW[32 * 128];
    __shared__ float2 sXd[64 * 32];  // [row][k], each entry (x,x)
    int tid = threadIdx.x;
    int warp = tid >> 5, lane = tid & 31;
    int row0 = blockIdx.x * 64;

    unsigned long long acc[8][2];
#pragma unroll
    for (int r = 0; r < 8; r++) { acc[r][0] = 0ull; acc[r][1] = 0ull; }

    for (int kt = 0; kt < 4; kt++) {
        const float4* Wf4 = reinterpret_cast<const float4*>(W) + kt * 1024;
        for (int i = tid; i < 1024; i += 256)
            reinterpret_cast<float4*>(sW)[i] = __ldg(Wf4 + i);
        for (int i = tid; i < 512; i += 256) {
            int r = i >> 3, kk = i & 7;
            float4 v = make_float4(0.f, 0.f, 0.f, 0.f);
            if (row0 + r < nrows)
                v = __ldg(reinterpret_cast<const float4*>(X) + (size_t)(row0 + r) * 32 + kt * 8 + kk);
            if (scale) {
                float4 sc = __ldg(reinterpret_cast<const float4*>(scale) + kt * 8 + kk);
                float4 sh = __ldg(reinterpret_cast<const float4*>(shift) + kt * 8 + kk);
                v.x = fmaxf(fmaf(v.x, sc.x, sh.x), 0.f);
                v.y = fmaxf(fmaf(v.y, sc.y, sh.y), 0.f);
                v.z = fmaxf(fmaf(v.z, sc.z, sh.z), 0.f);
                v.w = fmaxf(fmaf(v.w, sc.w, sh.w), 0.f);
            }
            float2* p = sXd + (r * 32 + kk * 4);
            p[0] = make_float2(v.x, v.x);
            p[1] = make_float2(v.y, v.y);
            p[2] = make_float2(v.z, v.z);
            p[3] = make_float2(v.w, v.w);
        }
        __syncthreads();
#pragma unroll
        for (int k = 0; k < 32; k++) {
            const unsigned long long* wp =
                reinterpret_cast<const unsigned long long*>(sW + k * 128) + lane * 2;
            unsigned long long w01 = wp[0], w23 = wp[1];
#pragma unroll
            for (int r = 0; r < 8; r++) {
                unsigned long long xv2 =
                    *reinterpret_cast<const unsigned long long*>(sXd + (warp * 8 + r) * 32 + k);
                acc[r][0] = ffma2(xv2, w01, acc[r][0]);
                acc[r][1] = ffma2(xv2, w23, acc[r][1]);
            }
        }
        __syncthreads();
    }
#pragma unroll
    for (int r = 0; r < 8; r++) {
        int row = row0 + warp * 8 + r;
        if (row < nrows) {
            float4 o;
            unpack2(acc[r][0], o.x, o.y);
            unpack2(acc[r][1], o.z, o.w);
            *(reinterpret_cast<float4*>(H + (size_t)row * DD) + lane) = o;
        }
    }
}

// ---------------- CSR pull aggregation + self + bias + stats ----------------
// One warp per node (16 nodes/warp sequentially), lane owns 4 columns.
__global__ __launch_bounds__(256) void k_agg(const float* __restrict__ H,
                                             const float* __restrict__ bias,
                                             float* __restrict__ T, int n) {
    __shared__ float ssum[DD];
    __shared__ float ssq[DD];
    int tid = threadIdx.x;
    int warp = tid >> 5, lane = tid & 31;
    if (tid < DD) { ssum[tid] = 0.f; ssq[tid] = 0.f; }
    __syncthreads();

    float4 b4 = __ldg(reinterpret_cast<const float4*>(bias) + lane);
    float ls[4] = {0.f, 0.f, 0.f, 0.f}, lq[4] = {0.f, 0.f, 0.f, 0.f};

    int base = blockIdx.x * 128 + warp * 16;
    int nodes = min(16, n - base);
    for (int nn = 0; nn < nodes; nn++) {
        int d = base + nn;
        float di = __ldg(g_dinv + d);
        float sw = di * di;
        float4 acc = __ldg(reinterpret_cast<const float4*>(H + (size_t)d * DD) + lane);
        acc.x = fmaf(acc.x, sw, b4.x);
        acc.y = fmaf(acc.y, sw, b4.y);
        acc.z = fmaf(acc.z, sw, b4.z);
        acc.w = fmaf(acc.w, sw, b4.w);
        int o0 = __ldg(g_off + d), o1 = __ldg(g_off + d + 1);
        for (int j = o0; j < o1; j++) {
            int s = __ldg(g_csr_src + j);
            float nm = __ldg(g_csr_norm + j);
            float4 v = __ldg(reinterpret_cast<const float4*>(H + (size_t)s * DD) + lane);
            acc.x = fmaf(v.x, nm, acc.x);
            acc.y = fmaf(v.y, nm, acc.y);
            acc.z = fmaf(v.z, nm, acc.z);
            acc.w = fmaf(v.w, nm, acc.w);
        }
        *(reinterpret_cast<float4*>(T + (size_t)d * DD) + lane) = acc;
        ls[0] += acc.x; ls[1] += acc.y; ls[2] += acc.z; ls[3] += acc.w;
        lq[0] += acc.x * acc.x; lq[1] += acc.y * acc.y;
        lq[2] += acc.z * acc.z; lq[3] += acc.w * acc.w;
    }
#pragma unroll
    for (int c = 0; c < 4; c++) {
        atomicAdd(&ssum[lane * 4 + c], ls[c]);
        atomicAdd(&ssq[lane * 4 + c], lq[c]);
    }
    __syncthreads();
    if (tid < DD) {
        atomicAdd(&g_stats[tid], ssum[tid]);
        atomicAdd(&g_stats[DD + tid], ssq[tid]);
    }
}

// ---------------- finalize: scale/shift from stats, reset stats ----------------
__global__ void k_finalize(const float* __restrict__ gamma,
                           const float* __restrict__ beta, float inv_n) {
    int c = threadIdx.x;
    float s = g_stats[c], ss = g_stats[DD + c];
    float mu = s * inv_n;
    float var = ss * inv_n - mu * mu;
    float rstd = rsqrtf(var + 1e-5f);
    float sc = __ldg(gamma + c) * rstd;
    g_scale[c] = sc;
    g_shift[c] = __ldg(beta + c) - mu * sc;
    g_stats[c] = 0.f;
    g_stats[DD + c] = 0.f;
}

// ---------------- final: out = relu(bn(t) + x) ----------------
__global__ __launch_bounds__(256) void k_bnfinal(float* __restrict__ out,
                                                 const float* __restrict__ resid, int n4) {
    int i = blockIdx.x * blockDim.x + threadIdx.x;
    if (i >= n4) return;
    int c4 = i & 31;
    float4 sc = reinterpret_cast<const float4*>(g_scale)[c4];
    float4 sh = reinterpret_cast<const float4*>(g_shift)[c4];
    float4 t = reinterpret_cast<const float4*>(g_t)[i];
    float4 rv = __ldg(reinterpret_cast<const float4*>(resid) + i);
    float4 r;
    r.x = fmaxf(fmaf(t.x, sc.x, sh.x) + rv.x, 0.f);
    r.y = fmaxf(fmaf(t.y, sc.y, sh.y) + rv.y, 0.f);
    r.z = fmaxf(fmaf(t.z, sc.z, sh.z) + rv.z, 0.f);
    r.w = fmaxf(fmaf(t.w, sc.w, sh.w) + rv.w, 0.f);
    reinterpret_cast<float4*>(out)[i] = r;
}

extern "C" void kernel_launch(void* const* d_in, const int* in_sizes, int n_in,
                              void* d_out, int out_size) {
    const float* x   = (const float*)d_in[0];
    const int*   ei  = (const int*)d_in[1];
    const float* W1  = (const float*)d_in[2];
    const float* b1  = (const float*)d_in[3];
    const float* ga1 = (const float*)d_in[4];
    const float* be1 = (const float*)d_in[5];
    const float* W2  = (const float*)d_in[6];
    const float* b2  = (const float*)d_in[7];
    const float* ga2 = (const float*)d_in[8];
    const float* be2 = (const float*)d_in[9];
    float* out = (float*)d_out;

    int n = in_sizes[0] / DD;
    int e = in_sizes[1] / 2;
    const int* src = ei;
    const int* dst = ei + e;
    int n4 = n * (DD / 4);
    float inv_n = 1.0f / (float)n;

    float *d_h, *d_t, *d_scale, *d_shift;
    cudaGetSymbolAddress((void**)&d_h, g_h);
    cudaGetSymbolAddress((void**)&d_t, g_t);
    cudaGetSymbolAddress((void**)&d_scale, g_scale);
    cudaGetSymbolAddress((void**)&d_shift, g_shift);

    dim3 b256(256);
    int gN    = (n + 255) / 256;
    int gE    = (e + 255) / 256;
    int gGemm = (n + 63) / 64;
    int gAgg  = (n + 127) / 128;
    int gBn   = (n4 + 255) / 256;

    // ---- graph prep (CSR) ----
    k_init<<<gN, b256>>>(n);
    k_degree<<<gE, b256>>>(dst, e);
    k_scan<<<1, 1024>>>(n);
    k_fill<<<gE, b256>>>(src, dst, e);

    // ---- layer 1 ----
    k_gemm<<<gGemm, b256>>>(x, W1, d_h, n, nullptr, nullptr);
    k_agg<<<gAgg, b256>>>(d_h, b1, d_t, n);
    k_finalize<<<1, DD>>>(ga1, be1, inv_n);

    // ---- layer 2 (BN1+ReLU fused into GEMM2's X load) ----
    k_gemm<<<gGemm, b256>>>(d_t, W2, d_h, n, d_scale, d_shift);
    k_agg<<<gAgg, b256>>>(d_h, b2, d_t, n);
    k_finalize<<<1, DD>>>(ga2, be2, inv_n);

    // ---- epilogue ----
    k_bnfinal<<<gBn, b256>>>(out, x, n4);
}

// round 3
// speedup vs baseline: 1.2104x; 1.2104x over previous
#include <cuda_runtime.h>
#include <cuda_bf16.h>
#include <cstdint>

#define ND 50000
#define ED 800000
#define DD 128

// ---------------- scratch (device globals) ----------------
__device__ int   g_cnt[ND];        // in-degree (edges only)
__device__ float g_dinv[ND];
__device__ int   g_off[ND + 1];
__device__ int   g_cur[ND];
__device__ int   g_part[256];
__device__ int   g_csr_src[ED];
__device__ float g_csr_norm[ED];
__device__ float g_h[ND * DD];     // X @ W
__device__ float g_t[ND * DD];     // pre-BN conv output
__device__ float g_stats[2 * DD];  // col sums / sumsq
__device__ float g_scale[DD];
__device__ float g_shift[DD];

// ---------------- f32x2 helpers ----------------
__device__ __forceinline__ unsigned long long ffma2(unsigned long long a,
                                                    unsigned long long b,
                                                    unsigned long long c) {
    unsigned long long d;
    asm("fma.rn.f32x2 %0, %1, %2, %3;" : "=l"(d) : "l"(a), "l"(b), "l"(c));
    return d;
}
__device__ __forceinline__ void unpack2(unsigned long long v, float& lo, float& hi) {
    asm("mov.b64 {%0, %1}, %2;" : "=f"(lo), "=f"(hi) : "l"(v));
}

// ---------------- prep ----------------
__global__ void k_zero(int n) {
    int i = blockIdx.x * blockDim.x + threadIdx.x;
    if (i < n) g_cnt[i] = 0;
    if (i < 2 * DD) g_stats[i] = 0.0f;
}

__global__ void k_degcnt(const int* __restrict__ dst, int e) {
    int i = blockIdx.x * blockDim.x + threadIdx.x;
    if (i < e) atomicAdd(&g_cnt[dst[i]], 1);
}

// scan phase 1: per-256-tile exclusive scan, tile totals to g_part
__global__ __launch_bounds__(256) void k_scan1(int n) {
    __shared__ int sm[256];
    int tid = threadIdx.x;
    int i = blockIdx.x * 256 + tid;
    int d = (i < n) ? g_cnt[i] : 0;
    sm[tid] = d;
    __syncthreads();
    for (int off = 1; off < 256; off <<= 1) {
        int v = (tid >= off) ? sm[tid - off] : 0;
        __syncthreads();
        sm[tid] += v;
        __syncthreads();
    }
    if (i < n) g_off[i] = sm[tid] - d;  // exclusive within tile
    if (tid == 255) g_part[blockIdx.x] = sm[255];
}

// scan phase 2: single block scans tile totals (exclusive), writes g_off[n]
__global__ __launch_bounds__(256) void k_scan2(int nblocks, int n) {
    __shared__ int sm[256];
    int tid = threadIdx.x;
    int d = (tid < nblocks) ? g_part[tid] : 0;
    sm[tid] = d;
    __syncthreads();
    for (int off = 1; off < 256; off <<= 1) {
        int v = (tid >= off) ? sm[tid - off] : 0;
        __syncthreads();
        sm[tid] += v;
        __syncthreads();
    }
    if (tid < nblocks) g_part[tid] = sm[tid] - d;
    if (tid == nblocks - 1) g_off[n] = sm[tid];
}

// scan phase 3: add tile base; init cursors + dinv
__global__ __launch_bounds__(256) void k_scan3(int n) {
    int i = blockIdx.x * 256 + threadIdx.x;
    if (i < n) {
        int o = g_off[i] + g_part[blockIdx.x];
        g_off[i] = o;
        g_cur[i] = o;
        g_dinv[i] = rsqrtf((float)(g_cnt[i] + 1));
    }
}

__global__ void k_fill(const int* __restrict__ src, const int* __restrict__ dst, int e) {
    int i = blockIdx.x * blockDim.x + threadIdx.x;
    if (i >= e) return;
    int s = src[i], d = dst[i];
    int pos = atomicAdd(&g_cur[d], 1);
    g_csr_src[pos] = s;
    g_csr_norm[pos] = g_dinv[s] * g_dinv[d];
}

// ---------------- GEMM: H = act(X) @ W via packed f32x2 ----------------
__global__ __launch_bounds__(256) void k_gemm(const float* __restrict__ X,
                                              const float* __restrict__ W,
                                              float* __restrict__ H, int nrows,
                                              const float* __restrict__ scale,
                                              const float* __restrict__ shift) {
    __shared__ float sW[32 * 128];
    __shared__ float2 sXd[64 * 32];  // [row][k], each entry (x,x)
    int tid = threadIdx.x;
    int warp = tid >> 5, lane = tid & 31;
    int row0 = blockIdx.x * 64;

    unsigned long long acc[8][2];
#pragma unroll
    for (int r = 0; r < 8; r++) { acc[r][0] = 0ull; acc[r][1] = 0ull; }

    for (int kt = 0; kt < 4; kt++) {
        const float4* Wf4 = reinterpret_cast<const float4*>(W) + kt * 1024;
        for (int i = tid; i < 1024; i += 256)
            reinterpret_cast<float4*>(sW)[i] = __ldg(Wf4 + i);
        for (int i = tid; i < 512; i += 256) {
            int r = i >> 3, kk = i & 7;
            float4 v = make_float4(0.f, 0.f, 0.f, 0.f);
            if (row0 + r < nrows)
                v = __ldg(reinterpret_cast<const float4*>(X) + (size_t)(row0 + r) * 32 + kt * 8 + kk);
            if (scale) {
                float4 sc = __ldg(reinterpret_cast<const float4*>(scale) + kt * 8 + kk);
                float4 sh = __ldg(reinterpret_cast<const float4*>(shift) + kt * 8 + kk);
                v.x = fmaxf(fmaf(v.x, sc.x, sh.x), 0.f);
                v.y = fmaxf(fmaf(v.y, sc.y, sh.y), 0.f);
                v.z = fmaxf(fmaf(v.z, sc.z, sh.z), 0.f);
                v.w = fmaxf(fmaf(v.w, sc.w, sh.w), 0.f);
            }
            float2* p = sXd + (r * 32 + kk * 4);
            p[0] = make_float2(v.x, v.x);
            p[1] = make_float2(v.y, v.y);
            p[2] = make_float2(v.z, v.z);
            p[3] = make_float2(v.w, v.w);
        }
        __syncthreads();
#pragma unroll
        for (int k = 0; k < 32; k++) {
            const unsigned long long* wp =
                reinterpret_cast<const unsigned long long*>(sW + k * 128) + lane * 2;
            unsigned long long w01 = wp[0], w23 = wp[1];
#pragma unroll
            for (int r = 0; r < 8; r++) {
                unsigned long long xv2 =
                    *reinterpret_cast<const unsigned long long*>(sXd + (warp * 8 + r) * 32 + k);
                acc[r][0] = ffma2(xv2, w01, acc[r][0]);
                acc[r][1] = ffma2(xv2, w23, acc[r][1]);
            }
        }
        __syncthreads();
    }
#pragma unroll
    for (int r = 0; r < 8; r++) {
        int row = row0 + warp * 8 + r;
        if (row < nrows) {
            float4 o;
            unpack2(acc[r][0], o.x, o.y);
            unpack2(acc[r][1], o.z, o.w);
            *(reinterpret_cast<float4*>(H + (size_t)row * DD) + lane) = o;
        }
    }
}

// ---------------- CSR pull aggregation, column-parallel, MLP-4 ----------------
// 256 threads = 2 column-slabs of 128; thread owns one column. 16 nodes/slab.
__global__ __launch_bounds__(256) void k_agg(const float* __restrict__ H,
                                             const float* __restrict__ bias,
                                             float* __restrict__ T, int n) {
    __shared__ float ssum[256];
    __shared__ float ssq[256];
    int tid = threadIdx.x;
    int slab = tid >> 7;
    int t = tid & 127;
    float b = __ldg(bias + t);
    int base = blockIdx.x * 32 + slab * 16;
    float ls = 0.f, lq = 0.f;
    int nodes = n - base;
    if (nodes > 16) nodes = 16;

    for (int nn = 0; nn < nodes; nn++) {
        int d = base + nn;
        float di = __ldg(g_dinv + d);
        float acc = fmaf(__ldg(H + (size_t)d * DD + t), di * di, b);
        int j = __ldg(g_off + d);
        int o1 = __ldg(g_off + d + 1);
        for (; j + 4 <= o1; j += 4) {
            int s0 = __ldg(g_csr_src + j);
            int s1 = __ldg(g_csr_src + j + 1);
            int s2 = __ldg(g_csr_src + j + 2);
            int s3 = __ldg(g_csr_src + j + 3);
            float n0 = __ldg(g_csr_norm + j);
            float n1 = __ldg(g_csr_norm + j + 1);
            float n2 = __ldg(g_csr_norm + j + 2);
            float n3 = __ldg(g_csr_norm + j + 3);
            float v0 = __ldg(H + (size_t)s0 * DD + t);
            float v1 = __ldg(H + (size_t)s1 * DD + t);
            float v2 = __ldg(H + (size_t)s2 * DD + t);
            float v3 = __ldg(H + (size_t)s3 * DD + t);
            acc = fmaf(v0, n0, acc);
            acc = fmaf(v1, n1, acc);
            acc = fmaf(v2, n2, acc);
            acc = fmaf(v3, n3, acc);
        }
        for (; j < o1; j++) {
            int s = __ldg(g_csr_src + j);
            float nm = __ldg(g_csr_norm + j);
            acc = fmaf(__ldg(H + (size_t)s * DD + t), nm, acc);
        }
        T[(size_t)d * DD + t] = acc;
        ls += acc;
        lq += acc * acc;
    }
    ssum[tid] = ls;
    ssq[tid] = lq;
    __syncthreads();
    if (tid < DD) {
        atomicAdd(&g_stats[tid], ssum[tid] + ssum[tid + DD]);
        atomicAdd(&g_stats[DD + tid], ssq[tid] + ssq[tid + DD]);
    }
}

// ---------------- finalize: scale/shift from stats, reset stats ----------------
__global__ void k_finalize(const float* __restrict__ gamma,
                           const float* __restrict__ beta, float inv_n) {
    int c = threadIdx.x;
    float s = g_stats[c], ss = g_stats[DD + c];
    float mu = s * inv_n;
    float var = ss * inv_n - mu * mu;
    float rstd = rsqrtf(var + 1e-5f);
    float sc = __ldg(gamma + c) * rstd;
    g_scale[c] = sc;
    g_shift[c] = __ldg(beta + c) - mu * sc;
    g_stats[c] = 0.f;
    g_stats[DD + c] = 0.f;
}

// ---------------- final: out = relu(bn(t) + x) ----------------
__global__ __launch_bounds__(256) void k_bnfinal(float* __restrict__ out,
                                                 const float* __restrict__ resid, int n4) {
    int i = blockIdx.x * blockDim.x + threadIdx.x;
    if (i >= n4) return;
    int c4 = i & 31;
    float4 sc = reinterpret_cast<const float4*>(g_scale)[c4];
    float4 sh = reinterpret_cast<const float4*>(g_shift)[c4];
    float4 t = reinterpret_cast<const float4*>(g_t)[i];
    float4 rv = __ldg(reinterpret_cast<const float4*>(resid) + i);
    float4 r;
    r.x = fmaxf(fmaf(t.x, sc.x, sh.x) + rv.x, 0.f);
    r.y = fmaxf(fmaf(t.y, sc.y, sh.y) + rv.y, 0.f);
    r.z = fmaxf(fmaf(t.z, sc.z, sh.z) + rv.z, 0.f);
    r.w = fmaxf(fmaf(t.w, sc.w, sh.w) + rv.w, 0.f);
    reinterpret_cast<float4*>(out)[i] = r;
}

extern "C" void kernel_launch(void* const* d_in, const int* in_sizes, int n_in,
                              void* d_out, int out_size) {
    const float* x   = (const float*)d_in[0];
    const int*   ei  = (const int*)d_in[1];
    const float* W1  = (const float*)d_in[2];
    const float* b1  = (const float*)d_in[3];
    const float* ga1 = (const float*)d_in[4];
    const float* be1 = (const float*)d_in[5];
    const float* W2  = (const float*)d_in[6];
    const float* b2  = (const float*)d_in[7];
    const float* ga2 = (const float*)d_in[8];
    const float* be2 = (const float*)d_in[9];
    float* out = (float*)d_out;

    int n = in_sizes[0] / DD;
    int e = in_sizes[1] / 2;
    const int* src = ei;
    const int* dst = ei + e;
    int n4 = n * (DD / 4);
    float inv_n = 1.0f / (float)n;

    float *d_h, *d_t, *d_scale, *d_shift;
    cudaGetSymbolAddress((void**)&d_h, g_h);
    cudaGetSymbolAddress((void**)&d_t, g_t);
    cudaGetSymbolAddress((void**)&d_scale, g_scale);
    cudaGetSymbolAddress((void**)&d_shift, g_shift);

    dim3 b256(256);
    int gN    = (n + 255) / 256;       // 196 (also the scan tile count)
    int gE    = (e + 255) / 256;
    int gGemm = (n + 63) / 64;
    int gAgg  = (n + 31) / 32;
    int gBn   = (n4 + 255) / 256;

    // ---- graph prep (CSR) ----
    k_zero<<<gN, b256>>>(n);
    k_degcnt<<<gE, b256>>>(dst, e);
    k_scan1<<<gN, b256>>>(n);
    k_scan2<<<1, b256>>>(gN, n);
    k_scan3<<<gN, b256>>>(n);
    k_fill<<<gE, b256>>>(src, dst, e);

    // ---- layer 1 ----
    k_gemm<<<gGemm, b256>>>(x, W1, d_h, n, nullptr, nullptr);
    k_agg<<<gAgg, b256>>>(d_h, b1, d_t, n);
    k_finalize<<<1, DD>>>(ga1, be1, inv_n);

    // ---- layer 2 (BN1+ReLU fused into GEMM2's X load) ----
    k_gemm<<<gGemm, b256>>>(d_t, W2, d_h, n, d_scale, d_shift);
    k_agg<<<gAgg, b256>>>(d_h, b2, d_t, n);
    k_finalize<<<1, DD>>>(ga2, be2, inv_n);

    // ---- epilogue ----
    k_bnfinal<<<gBn, b256>>>(out, x, n4);
}

// round 4
// speedup vs baseline: 1.5203x; 1.2561x over previous
#include <cuda_runtime.h>
#include <cuda_bf16.h>
#include <cstdint>

#define ND 50000
#define ED 800000
#define DD 128

// ---------------- scratch (device globals) ----------------
__device__ int   g_cnt[ND];
__device__ float g_dinv[ND];
__device__ int   g_off[ND + 1];
__device__ int   g_cur[ND];
__device__ int   g_part[256];
__device__ int2  g_csr[ED];        // (src, norm-as-int-bits)
__device__ float g_h[ND * DD];     // X @ W
__device__ float g_t[ND * DD];     // pre-BN conv output
__device__ float g_stats[2 * DD];
__device__ float g_scale[DD];
__device__ float g_shift[DD];

// ---------------- f32x2 helpers ----------------
__device__ __forceinline__ unsigned long long ffma2(unsigned long long a,
                                                    unsigned long long b,
                                                    unsigned long long c) {
    unsigned long long d;
    asm("fma.rn.f32x2 %0, %1, %2, %3;" : "=l"(d) : "l"(a), "l"(b), "l"(c));
    return d;
}
__device__ __forceinline__ void unpack2(unsigned long long v, float& lo, float& hi) {
    asm("mov.b64 {%0, %1}, %2;" : "=f"(lo), "=f"(hi) : "l"(v));
}

// ---------------- prep ----------------
__global__ void k_zero(int n) {
    int i = blockIdx.x * blockDim.x + threadIdx.x;
    if (i < n) g_cnt[i] = 0;
    if (i < 2 * DD) g_stats[i] = 0.0f;
}

__global__ void k_degcnt(const int* __restrict__ dst, int e) {
    int i = blockIdx.x * blockDim.x + threadIdx.x;
    if (i < e) atomicAdd(&g_cnt[dst[i]], 1);
}

// scan phase 1: per-256-tile exclusive scan, tile totals to g_part
__global__ __launch_bounds__(256) void k_scan1(int n) {
    __shared__ int sm[256];
    int tid = threadIdx.x;
    int i = blockIdx.x * 256 + tid;
    int d = (i < n) ? g_cnt[i] : 0;
    sm[tid] = d;
    __syncthreads();
    for (int off = 1; off < 256; off <<= 1) {
        int v = (tid >= off) ? sm[tid - off] : 0;
        __syncthreads();
        sm[tid] += v;
        __syncthreads();
    }
    if (i < n) g_off[i] = sm[tid] - d;
    if (tid == 255) g_part[blockIdx.x] = sm[255];
}

// scan phase 2: single block scans tile totals
__global__ __launch_bounds__(256) void k_scan2(int nblocks, int n) {
    __shared__ int sm[256];
    int tid = threadIdx.x;
    int d = (tid < nblocks) ? g_part[tid] : 0;
    sm[tid] = d;
    __syncthreads();
    for (int off = 1; off < 256; off <<= 1) {
        int v = (tid >= off) ? sm[tid - off] : 0;
        __syncthreads();
        sm[tid] += v;
        __syncthreads();
    }
    if (tid < nblocks) g_part[tid] = sm[tid] - d;
    if (tid == nblocks - 1) g_off[n] = sm[tid];
}

// scan phase 3: add tile base; init cursors + dinv
__global__ __launch_bounds__(256) void k_scan3(int n) {
    int i = blockIdx.x * 256 + threadIdx.x;
    if (i < n) {
        int o = g_off[i] + g_part[blockIdx.x];
        g_off[i] = o;
        g_cur[i] = o;
        g_dinv[i] = rsqrtf((float)(g_cnt[i] + 1));
    }
}

__global__ void k_fill(const int* __restrict__ src, const int* __restrict__ dst, int e) {
    int i = blockIdx.x * blockDim.x + threadIdx.x;
    if (i >= e) return;
    int s = src[i], d = dst[i];
    int pos = atomicAdd(&g_cur[d], 1);
    float nm = __ldg(g_dinv + s) * __ldg(g_dinv + d);
    g_csr[pos] = make_int2(s, __float_as_int(nm));
}

// ---------------- GEMM: H = act(X) @ W via packed f32x2 ----------------
__global__ __launch_bounds__(256) void k_gemm(const float* __restrict__ X,
                                              const float* __restrict__ W,
                                              float* __restrict__ H, int nrows,
                                              const float* __restrict__ scale,
                                              const float* __restrict__ shift) {
    __shared__ float sW[32 * 128];
    __shared__ float2 sXd[64 * 32];
    int tid = threadIdx.x;
    int warp = tid >> 5, lane = tid & 31;
    int row0 = blockIdx.x * 64;

    unsigned long long acc[8][2];
#pragma unroll
    for (int r = 0; r < 8; r++) { acc[r][0] = 0ull; acc[r][1] = 0ull; }

    for (int kt = 0; kt < 4; kt++) {
        const float4* Wf4 = reinterpret_cast<const float4*>(W) + kt * 1024;
        for (int i = tid; i < 1024; i += 256)
            reinterpret_cast<float4*>(sW)[i] = __ldg(Wf4 + i);
        for (int i = tid; i < 512; i += 256) {
            int r = i >> 3, kk = i & 7;
            float4 v = make_float4(0.f, 0.f, 0.f, 0.f);
            if (row0 + r < nrows)
                v = __ldg(reinterpret_cast<const float4*>(X) + (size_t)(row0 + r) * 32 + kt * 8 + kk);
            if (scale) {
                float4 sc = __ldg(reinterpret_cast<const float4*>(scale) + kt * 8 + kk);
                float4 sh = __ldg(reinterpret_cast<const float4*>(shift) + kt * 8 + kk);
                v.x = fmaxf(fmaf(v.x, sc.x, sh.x), 0.f);
                v.y = fmaxf(fmaf(v.y, sc.y, sh.y), 0.f);
                v.z = fmaxf(fmaf(v.z, sc.z, sh.z), 0.f);
                v.w = fmaxf(fmaf(v.w, sc.w, sh.w), 0.f);
            }
            float2* p = sXd + (r * 32 + kk * 4);
            p[0] = make_float2(v.x, v.x);
            p[1] = make_float2(v.y, v.y);
            p[2] = make_float2(v.z, v.z);
            p[3] = make_float2(v.w, v.w);
        }
        __syncthreads();
#pragma unroll
        for (int k = 0; k < 32; k++) {
            const unsigned long long* wp =
                reinterpret_cast<const unsigned long long*>(sW + k * 128) + lane * 2;
            unsigned long long w01 = wp[0], w23 = wp[1];
#pragma unroll
            for (int r = 0; r < 8; r++) {
                unsigned long long xv2 =
                    *reinterpret_cast<const unsigned long long*>(sXd + (warp * 8 + r) * 32 + k);
                acc[r][0] = ffma2(xv2, w01, acc[r][0]);
                acc[r][1] = ffma2(xv2, w23, acc[r][1]);
            }
        }
        __syncthreads();
    }
#pragma unroll
    for (int r = 0; r < 8; r++) {
        int row = row0 + warp * 8 + r;
        if (row < nrows) {
            float4 o;
            unpack2(acc[r][0], o.x, o.y);
            unpack2(acc[r][1], o.z, o.w);
            *(reinterpret_cast<float4*>(H + (size_t)row * DD) + lane) = o;
        }
    }
}

// ---------------- CSR pull aggregation: warp-per-node, float4 lanes, MLP-4 ----
// 256 threads = 8 warps; warp handles 4 nodes; block = 32 nodes.
__global__ __launch_bounds__(256) void k_agg(const float* __restrict__ H,
                                             const float* __restrict__ bias,
                                             float* __restrict__ T, int n) {
    __shared__ float ssum[DD];
    __shared__ float ssq[DD];
    int tid = threadIdx.x;
    int warp = tid >> 5, lane = tid & 31;
    if (tid < DD) { ssum[tid] = 0.f; ssq[tid] = 0.f; }
    __syncthreads();

    float4 b4 = __ldg(reinterpret_cast<const float4*>(bias) + lane);
    float ls[4] = {0.f, 0.f, 0.f, 0.f}, lq[4] = {0.f, 0.f, 0.f, 0.f};
    int base = blockIdx.x * 32 + warp * 4;

#pragma unroll
    for (int nn = 0; nn < 4; nn++) {
        int d = base + nn;
        if (d >= n) break;
        float di = __ldg(g_dinv + d);
        float sw = di * di;
        float4 acc = __ldg(reinterpret_cast<const float4*>(H + (size_t)d * DD) + lane);
        acc.x = fmaf(acc.x, sw, b4.x);
        acc.y = fmaf(acc.y, sw, b4.y);
        acc.z = fmaf(acc.z, sw, b4.z);
        acc.w = fmaf(acc.w, sw, b4.w);
        int j = __ldg(g_off + d);
        int j1 = __ldg(g_off + d + 1);
        for (; j + 4 <= j1; j += 4) {
            int2 e0 = __ldg(g_csr + j);
            int2 e1 = __ldg(g_csr + j + 1);
            int2 e2 = __ldg(g_csr + j + 2);
            int2 e3 = __ldg(g_csr + j + 3);
            float4 v0 = __ldg(reinterpret_cast<const float4*>(H + (size_t)e0.x * DD) + lane);
            float4 v1 = __ldg(reinterpret_cast<const float4*>(H + (size_t)e1.x * DD) + lane);
            float4 v2 = __ldg(reinterpret_cast<const float4*>(H + (size_t)e2.x * DD) + lane);
            float4 v3 = __ldg(reinterpret_cast<const float4*>(H + (size_t)e3.x * DD) + lane);
            float n0 = __int_as_float(e0.y), n1 = __int_as_float(e1.y);
            float n2 = __int_as_float(e2.y), n3 = __int_as_float(e3.y);
            acc.x = fmaf(v0.x, n0, acc.x); acc.y = fmaf(v0.y, n0, acc.y);
            acc.z = fmaf(v0.z, n0, acc.z); acc.w = fmaf(v0.w, n0, acc.w);
            acc.x = fmaf(v1.x, n1, acc.x); acc.y = fmaf(v1.y, n1, acc.y);
            acc.z = fmaf(v1.z, n1, acc.z); acc.w = fmaf(v1.w, n1, acc.w);
            acc.x = fmaf(v2.x, n2, acc.x); acc.y = fmaf(v2.y, n2, acc.y);
            acc.z = fmaf(v2.z, n2, acc.z); acc.w = fmaf(v2.w, n2, acc.w);
            acc.x = fmaf(v3.x, n3, acc.x); acc.y = fmaf(v3.y, n3, acc.y);
            acc.z = fmaf(v3.z, n3, acc.z); acc.w = fmaf(v3.w, n3, acc.w);
        }
        for (; j < j1; j++) {
            int2 e = __ldg(g_csr + j);
            float4 v = __ldg(reinterpret_cast<const float4*>(H + (size_t)e.x * DD) + lane);
            float nm = __int_as_float(e.y);
            acc.x = fmaf(v.x, nm, acc.x); acc.y = fmaf(v.y, nm, acc.y);
            acc.z = fmaf(v.z, nm, acc.z); acc.w = fmaf(v.w, nm, acc.w);
        }
        *(reinterpret_cast<float4*>(T + (size_t)d * DD) + lane) = acc;
        ls[0] += acc.x; ls[1] += acc.y; ls[2] += acc.z; ls[3] += acc.w;
        lq[0] += acc.x * acc.x; lq[1] += acc.y * acc.y;
        lq[2] += acc.z * acc.z; lq[3] += acc.w * acc.w;
    }
#pragma unroll
    for (int c = 0; c < 4; c++) {
        atomicAdd(&ssum[lane * 4 + c], ls[c]);
        atomicAdd(&ssq[lane * 4 + c], lq[c]);
    }
    __syncthreads();
    if (tid < DD) {
        atomicAdd(&g_stats[tid], ssum[tid]);
        atomicAdd(&g_stats[DD + tid], ssq[tid]);
    }
}

// ---------------- finalize: scale/shift from stats, reset stats ----------------
__global__ void k_finalize(const float* __restrict__ gamma,
                           const float* __restrict__ beta, float inv_n) {
    int c = threadIdx.x;
    float s = g_stats[c], ss = g_stats[DD + c];
    float mu = s * inv_n;
    float var = ss * inv_n - mu * mu;
    float rstd = rsqrtf(var + 1e-5f);
    float sc = __ldg(gamma + c) * rstd;
    g_scale[c] = sc;
    g_shift[c] = __ldg(beta + c) - mu * sc;
    g_stats[c] = 0.f;
    g_stats[DD + c] = 0.f;
}

// ---------------- final: out = relu(bn(t) + x) ----------------
__global__ __launch_bounds__(256) void k_bnfinal(float* __restrict__ out,
                                                 const float* __restrict__ resid, int n4) {
    int i = blockIdx.x * blockDim.x + threadIdx.x;
    if (i >= n4) return;
    int c4 = i & 31;
    float4 sc = reinterpret_cast<const float4*>(g_scale)[c4];
    float4 sh = reinterpret_cast<const float4*>(g_shift)[c4];
    float4 t = reinterpret_cast<const float4*>(g_t)[i];
    float4 rv = __ldg(reinterpret_cast<const float4*>(resid) + i);
    float4 r;
    r.x = fmaxf(fmaf(t.x, sc.x, sh.x) + rv.x, 0.f);
    r.y = fmaxf(fmaf(t.y, sc.y, sh.y) + rv.y, 0.f);
    r.z = fmaxf(fmaf(t.z, sc.z, sh.z) + rv.z, 0.f);
    r.w = fmaxf(fmaf(t.w, sc.w, sh.w) + rv.w, 0.f);
    reinterpret_cast<float4*>(out)[i] = r;
}

extern "C" void kernel_launch(void* const* d_in, const int* in_sizes, int n_in,
                              void* d_out, int out_size) {
    const float* x   = (const float*)d_in[0];
    const int*   ei  = (const int*)d_in[1];
    const float* W1  = (const float*)d_in[2];
    const float* b1  = (const float*)d_in[3];
    const float* ga1 = (const float*)d_in[4];
    const float* be1 = (const float*)d_in[5];
    const float* W2  = (const float*)d_in[6];
    const float* b2  = (const float*)d_in[7];
    const float* ga2 = (const float*)d_in[8];
    const float* be2 = (const float*)d_in[9];
    float* out = (float*)d_out;

    int n = in_sizes[0] / DD;
    int e = in_sizes[1] / 2;
    const int* src = ei;
    const int* dst = ei + e;
    int n4 = n * (DD / 4);
    float inv_n = 1.0f / (float)n;

    float *d_h, *d_t, *d_scale, *d_shift;
    cudaGetSymbolAddress((void**)&d_h, g_h);
    cudaGetSymbolAddress((void**)&d_t, g_t);
    cudaGetSymbolAddress((void**)&d_scale, g_scale);
    cudaGetSymbolAddress((void**)&d_shift, g_shift);

    dim3 b256(256);
    int gN    = (n + 255) / 256;
    int gE    = (e + 255) / 256;
    int gGemm = (n + 63) / 64;
    int gAgg  = (n + 31) / 32;
    int gBn   = (n4 + 255) / 256;

    // ---- graph prep (CSR) ----
    k_zero<<<gN, b256>>>(n);
    k_degcnt<<<gE, b256>>>(dst, e);
    k_scan1<<<gN, b256>>>(n);
    k_scan2<<<1, b256>>>(gN, n);
    k_scan3<<<gN, b256>>>(n);
    k_fill<<<gE, b256>>>(src, dst, e);

    // ---- layer 1 ----
    k_gemm<<<gGemm, b256>>>(x, W1, d_h, n, nullptr, nullptr);
    k_agg<<<gAgg, b256>>>(d_h, b1, d_t, n);
    k_finalize<<<1, DD>>>(ga1, be1, inv_n);

    // ---- layer 2 (BN1+ReLU fused into GEMM2's X load) ----
    k_gemm<<<gGemm, b256>>>(d_t, W2, d_h, n, d_scale, d_shift);
    k_agg<<<gAgg, b256>>>(d_h, b2, d_t, n);
    k_finalize<<<1, DD>>>(ga2, be2, inv_n);

    // ---- epilogue ----
    k_bnfinal<<<gBn, b256>>>(out, x, n4);
}

// round 5
// speedup vs baseline: 1.5851x; 1.0426x over previous
#include <cuda_runtime.h>
#include <cuda_bf16.h>
#include <cstdint>

#define ND 50000
#define ED 800000
#define DD 128

// ---------------- scratch (device globals) ----------------
__device__ int   g_cnt[ND];
__device__ float g_dinv[ND];
__device__ int   g_off[ND + 1];
__device__ int   g_cur[ND];
__device__ int   g_part[256];
__device__ int   g_csr_src[ED];
__device__ float g_h[ND * DD];     // X @ W
__device__ float g_t[ND * DD];     // pre-BN conv output
__device__ float g_stats[2 * DD];
__device__ float g_scale[DD];
__device__ float g_shift[DD];

// ---------------- f32x2 helpers ----------------
__device__ __forceinline__ unsigned long long ffma2(unsigned long long a,
                                                    unsigned long long b,
                                                    unsigned long long c) {
    unsigned long long d;
    asm("fma.rn.f32x2 %0, %1, %2, %3;" : "=l"(d) : "l"(a), "l"(b), "l"(c));
    return d;
}
__device__ __forceinline__ void unpack2(unsigned long long v, float& lo, float& hi) {
    asm("mov.b64 {%0, %1}, %2;" : "=f"(lo), "=f"(hi) : "l"(v));
}

// ---------------- prep ----------------
__global__ void k_zero(int n) {
    int i = blockIdx.x * blockDim.x + threadIdx.x;
    if (i < n) g_cnt[i] = 0;
    if (i < 2 * DD) g_stats[i] = 0.0f;
}

__global__ void k_degcnt(const int* __restrict__ dst, int e) {
    int i = blockIdx.x * blockDim.x + threadIdx.x;
    if (i < e) atomicAdd(&g_cnt[dst[i]], 1);
}

// scan phase 1: per-256-tile exclusive scan, tile totals to g_part
__global__ __launch_bounds__(256) void k_scan1(int n) {
    __shared__ int sm[256];
    int tid = threadIdx.x;
    int i = blockIdx.x * 256 + tid;
    int d = (i < n) ? g_cnt[i] : 0;
    sm[tid] = d;
    __syncthreads();
    for (int off = 1; off < 256; off <<= 1) {
        int v = (tid >= off) ? sm[tid - off] : 0;
        __syncthreads();
        sm[tid] += v;
        __syncthreads();
    }
    if (i < n) g_off[i] = sm[tid] - d;
    if (tid == 255) g_part[blockIdx.x] = sm[255];
}

// scan phase 2: single block scans tile totals
__global__ __launch_bounds__(256) void k_scan2(int nblocks, int n) {
    __shared__ int sm[256];
    int tid = threadIdx.x;
    int d = (tid < nblocks) ? g_part[tid] : 0;
    sm[tid] = d;
    __syncthreads();
    for (int off = 1; off < 256; off <<= 1) {
        int v = (tid >= off) ? sm[tid - off] : 0;
        __syncthreads();
        sm[tid] += v;
        __syncthreads();
    }
    if (tid < nblocks) g_part[tid] = sm[tid] - d;
    if (tid == nblocks - 1) g_off[n] = sm[tid];
}

// scan phase 3: add tile base; init cursors + dinv
__global__ __launch_bounds__(256) void k_scan3(int n) {
    int i = blockIdx.x * 256 + threadIdx.x;
    if (i < n) {
        int o = g_off[i] + g_part[blockIdx.x];
        g_off[i] = o;
        g_cur[i] = o;
        g_dinv[i] = rsqrtf((float)(g_cnt[i] + 1));
    }
}

__global__ void k_fill(const int* __restrict__ src, const int* __restrict__ dst, int e) {
    int i = blockIdx.x * blockDim.x + threadIdx.x;
    if (i >= e) return;
    int s = src[i], d = dst[i];
    int pos = atomicAdd(&g_cur[d], 1);
    g_csr_src[pos] = s;
}

// ---------------- GEMM: H = act(X) @ W via packed f32x2, k-unroll-2 ----------
__global__ __launch_bounds__(256) void k_gemm(const float* __restrict__ X,
                                              const float* __restrict__ W,
                                              float* __restrict__ H, int nrows,
                                              const float* __restrict__ scale,
                                              const float* __restrict__ shift) {
    __shared__ float sW[32 * 128];
    __shared__ float2 sXd[64 * 32];  // [row][k], each entry (x,x)
    int tid = threadIdx.x;
    int warp = tid >> 5, lane = tid & 31;
    int row0 = blockIdx.x * 64;

    unsigned long long acc[8][2];
#pragma unroll
    for (int r = 0; r < 8; r++) { acc[r][0] = 0ull; acc[r][1] = 0ull; }

    for (int kt = 0; kt < 4; kt++) {
        const float4* Wf4 = reinterpret_cast<const float4*>(W) + kt * 1024;
        for (int i = tid; i < 1024; i += 256)
            reinterpret_cast<float4*>(sW)[i] = __ldg(Wf4 + i);
        for (int i = tid; i < 512; i += 256) {
            int r = i >> 3, kk = i & 7;
            float4 v = make_float4(0.f, 0.f, 0.f, 0.f);
            if (row0 + r < nrows)
                v = __ldg(reinterpret_cast<const float4*>(X) + (size_t)(row0 + r) * 32 + kt * 8 + kk);
            if (scale) {
                float4 sc = __ldg(reinterpret_cast<const float4*>(scale) + kt * 8 + kk);
                float4 sh = __ldg(reinterpret_cast<const float4*>(shift) + kt * 8 + kk);
                v.x = fmaxf(fmaf(v.x, sc.x, sh.x), 0.f);
                v.y = fmaxf(fmaf(v.y, sc.y, sh.y), 0.f);
                v.z = fmaxf(fmaf(v.z, sc.z, sh.z), 0.f);
                v.w = fmaxf(fmaf(v.w, sc.w, sh.w), 0.f);
            }
            float2* p = sXd + (r * 32 + kk * 4);
            p[0] = make_float2(v.x, v.x);
            p[1] = make_float2(v.y, v.y);
            p[2] = make_float2(v.z, v.z);
            p[3] = make_float2(v.w, v.w);
        }
        __syncthreads();
#pragma unroll
        for (int k = 0; k < 32; k += 2) {
            const unsigned long long* wa =
                reinterpret_cast<const unsigned long long*>(sW + k * 128) + lane * 2;
            const unsigned long long* wb =
                reinterpret_cast<const unsigned long long*>(sW + (k + 1) * 128) + lane * 2;
            unsigned long long w01a = wa[0], w23a = wa[1];
            unsigned long long w01b = wb[0], w23b = wb[1];
#pragma unroll
            for (int r = 0; r < 8; r++) {
                ulonglong2 xv =
                    *reinterpret_cast<const ulonglong2*>(sXd + (warp * 8 + r) * 32 + k);
                acc[r][0] = ffma2(xv.x, w01a, acc[r][0]);
                acc[r][1] = ffma2(xv.x, w23a, acc[r][1]);
                acc[r][0] = ffma2(xv.y, w01b, acc[r][0]);
                acc[r][1] = ffma2(xv.y, w23b, acc[r][1]);
            }
        }
        __syncthreads();
    }
#pragma unroll
    for (int r = 0; r < 8; r++) {
        int row = row0 + warp * 8 + r;
        if (row < nrows) {
            float4 o;
            unpack2(acc[r][0], o.x, o.y);
            unpack2(acc[r][1], o.z, o.w);
            *(reinterpret_cast<float4*>(H + (size_t)row * DD) + lane) = o;
        }
    }
}

// ---------------- CSR pull aggregation: warp-per-node, float4 lanes, MLP-8 ----
// 256 threads = 8 warps; warp handles 4 nodes; block = 32 nodes.
__global__ __launch_bounds__(256) void k_agg(const float* __restrict__ H,
                                             const float* __restrict__ bias,
                                             float* __restrict__ T, int n) {
    __shared__ float ssum[DD];
    __shared__ float ssq[DD];
    int tid = threadIdx.x;
    int warp = tid >> 5, lane = tid & 31;
    if (tid < DD) { ssum[tid] = 0.f; ssq[tid] = 0.f; }
    __syncthreads();

    float4 b4 = __ldg(reinterpret_cast<const float4*>(bias) + lane);
    float ls[4] = {0.f, 0.f, 0.f, 0.f}, lq[4] = {0.f, 0.f, 0.f, 0.f};
    int base = blockIdx.x * 32 + warp * 4;

#pragma unroll
    for (int nn = 0; nn < 4; nn++) {
        int d = base + nn;
        if (d >= n) break;
        float di = __ldg(g_dinv + d);
        float4 acc = __ldg(reinterpret_cast<const float4*>(H + (size_t)d * DD) + lane);
        float sw = di * di;
        acc.x = fmaf(acc.x, sw, b4.x);
        acc.y = fmaf(acc.y, sw, b4.y);
        acc.z = fmaf(acc.z, sw, b4.z);
        acc.w = fmaf(acc.w, sw, b4.w);
        int j = __ldg(g_off + d);
        int j1 = __ldg(g_off + d + 1);
        for (; j + 8 <= j1; j += 8) {
            int s0 = __ldg(g_csr_src + j);
            int s1 = __ldg(g_csr_src + j + 1);
            int s2 = __ldg(g_csr_src + j + 2);
            int s3 = __ldg(g_csr_src + j + 3);
            int s4 = __ldg(g_csr_src + j + 4);
            int s5 = __ldg(g_csr_src + j + 5);
            int s6 = __ldg(g_csr_src + j + 6);
            int s7 = __ldg(g_csr_src + j + 7);
            float n0 = __ldg(g_dinv + s0) * di;
            float n1 = __ldg(g_dinv + s1) * di;
            float n2 = __ldg(g_dinv + s2) * di;
            float n3 = __ldg(g_dinv + s3) * di;
            float n4 = __ldg(g_dinv + s4) * di;
            float n5 = __ldg(g_dinv + s5) * di;
            float n6 = __ldg(g_dinv + s6) * di;
            float n7 = __ldg(g_dinv + s7) * di;
            float4 v0 = __ldg(reinterpret_cast<const float4*>(H + (size_t)s0 * DD) + lane);
            float4 v1 = __ldg(reinterpret_cast<const float4*>(H + (size_t)s1 * DD) + lane);
            float4 v2 = __ldg(reinterpret_cast<const float4*>(H + (size_t)s2 * DD) + lane);
            float4 v3 = __ldg(reinterpret_cast<const float4*>(H + (size_t)s3 * DD) + lane);
            float4 v4 = __ldg(reinterpret_cast<const float4*>(H + (size_t)s4 * DD) + lane);
            float4 v5 = __ldg(reinterpret_cast<const float4*>(H + (size_t)s5 * DD) + lane);
            float4 v6 = __ldg(reinterpret_cast<const float4*>(H + (size_t)s6 * DD) + lane);
            float4 v7 = __ldg(reinterpret_cast<const float4*>(H + (size_t)s7 * DD) + lane);
            acc.x = fmaf(v0.x, n0, acc.x); acc.y = fmaf(v0.y, n0, acc.y);
            acc.z = fmaf(v0.z, n0, acc.z); acc.w = fmaf(v0.w, n0, acc.w);
            acc.x = fmaf(v1.x, n1, acc.x); acc.y = fmaf(v1.y, n1, acc.y);
            acc.z = fmaf(v1.z, n1, acc.z); acc.w = fmaf(v1.w, n1, acc.w);
            acc.x = fmaf(v2.x, n2, acc.x); acc.y = fmaf(v2.y, n2, acc.y);
            acc.z = fmaf(v2.z, n2, acc.z); acc.w = fmaf(v2.w, n2, acc.w);
            acc.x = fmaf(v3.x, n3, acc.x); acc.y = fmaf(v3.y, n3, acc.y);
            acc.z = fmaf(v3.z, n3, acc.z); acc.w = fmaf(v3.w, n3, acc.w);
            acc.x = fmaf(v4.x, n4, acc.x); acc.y = fmaf(v4.y, n4, acc.y);
            acc.z = fmaf(v4.z, n4, acc.z); acc.w = fmaf(v4.w, n4, acc.w);
            acc.x = fmaf(v5.x, n5, acc.x); acc.y = fmaf(v5.y, n5, acc.y);
            acc.z = fmaf(v5.z, n5, acc.z); acc.w = fmaf(v5.w, n5, acc.w);
            acc.x = fmaf(v6.x, n6, acc.x); acc.y = fmaf(v6.y, n6, acc.y);
            acc.z = fmaf(v6.z, n6, acc.z); acc.w = fmaf(v6.w, n6, acc.w);
            acc.x = fmaf(v7.x, n7, acc.x); acc.y = fmaf(v7.y, n7, acc.y);
            acc.z = fmaf(v7.z, n7, acc.z); acc.w = fmaf(v7.w, n7, acc.w);
        }
        for (; j < j1; j++) {
            int s = __ldg(g_csr_src + j);
            float nm = __ldg(g_dinv + s) * di;
            float4 v = __ldg(reinterpret_cast<const float4*>(H + (size_t)s * DD) + lane);
            acc.x = fmaf(v.x, nm, acc.x); acc.y = fmaf(v.y, nm, acc.y);
            acc.z = fmaf(v.z, nm, acc.z); acc.w = fmaf(v.w, nm, acc.w);
        }
        *(reinterpret_cast<float4*>(T + (size_t)d * DD) + lane) = acc;
        ls[0] += acc.x; ls[1] += acc.y; ls[2] += acc.z; ls[3] += acc.w;
        lq[0] += acc.x * acc.x; lq[1] += acc.y * acc.y;
        lq[2] += acc.z * acc.z; lq[3] += acc.w * acc.w;
    }
#pragma unroll
    for (int c = 0; c < 4; c++) {
        atomicAdd(&ssum[lane * 4 + c], ls[c]);
        atomicAdd(&ssq[lane * 4 + c], lq[c]);
    }
    __syncthreads();
    if (tid < DD) {
        atomicAdd(&g_stats[tid], ssum[tid]);
        atomicAdd(&g_stats[DD + tid], ssq[tid]);
    }
}

// ---------------- finalize: scale/shift from stats, reset stats ----------------
__global__ void k_finalize(const float* __restrict__ gamma,
                           const float* __restrict__ beta, float inv_n) {
    int c = threadIdx.x;
    float s = g_stats[c], ss = g_stats[DD + c];
    float mu = s * inv_n;
    float var = ss * inv_n - mu * mu;
    float rstd = rsqrtf(var + 1e-5f);
    float sc = __ldg(gamma + c) * rstd;
    g_scale[c] = sc;
    g_shift[c] = __ldg(beta + c) - mu * sc;
    g_stats[c] = 0.f;
    g_stats[DD + c] = 0.f;
}

// ---------------- final: out = relu(bn(t) + x) ----------------
__global__ __launch_bounds__(256) void k_bnfinal(float* __restrict__ out,
                                                 const float* __restrict__ resid, int n4) {
    int i = blockIdx.x * blockDim.x + threadIdx.x;
    if (i >= n4) return;
    int c4 = i & 31;
    float4 sc = reinterpret_cast<const float4*>(g_scale)[c4];
    float4 sh = reinterpret_cast<const float4*>(g_shift)[c4];
    float4 t = reinterpret_cast<const float4*>(g_t)[i];
    float4 rv = __ldg(reinterpret_cast<const float4*>(resid) + i);
    float4 r;
    r.x = fmaxf(fmaf(t.x, sc.x, sh.x) + rv.x, 0.f);
    r.y = fmaxf(fmaf(t.y, sc.y, sh.y) + rv.y, 0.f);
    r.z = fmaxf(fmaf(t.z, sc.z, sh.z) + rv.z, 0.f);
    r.w = fmaxf(fmaf(t.w, sc.w, sh.w) + rv.w, 0.f);
    reinterpret_cast<float4*>(out)[i] = r;
}

extern "C" void kernel_launch(void* const* d_in, const int* in_sizes, int n_in,
                              void* d_out, int out_size) {
    const float* x   = (const float*)d_in[0];
    const int*   ei  = (const int*)d_in[1];
    const float* W1  = (const float*)d_in[2];
    const float* b1  = (const float*)d_in[3];
    const float* ga1 = (const float*)d_in[4];
    const float* be1 = (const float*)d_in[5];
    const float* W2  = (const float*)d_in[6];
    const float* b2  = (const float*)d_in[7];
    const float* ga2 = (const float*)d_in[8];
    const float* be2 = (const float*)d_in[9];
    float* out = (float*)d_out;

    int n = in_sizes[0] / DD;
    int e = in_sizes[1] / 2;
    const int* src = ei;
    const int* dst = ei + e;
    int n4 = n * (DD / 4);
    float inv_n = 1.0f / (float)n;

    float *d_h, *d_t, *d_scale, *d_shift;
    cudaGetSymbolAddress((void**)&d_h, g_h);
    cudaGetSymbolAddress((void**)&d_t, g_t);
    cudaGetSymbolAddress((void**)&d_scale, g_scale);
    cudaGetSymbolAddress((void**)&d_shift, g_shift);

    dim3 b256(256);
    int gN    = (n + 255) / 256;
    int gE    = (e + 255) / 256;
    int gGemm = (n + 63) / 64;
    int gAgg  = (n + 31) / 32;
    int gBn   = (n4 + 255) / 256;

    // ---- graph prep (CSR) ----
    k_zero<<<gN, b256>>>(n);
    k_degcnt<<<gE, b256>>>(dst, e);
    k_scan1<<<gN, b256>>>(n);
    k_scan2<<<1, b256>>>(gN, n);
    k_scan3<<<gN, b256>>>(n);
    k_fill<<<gE, b256>>>(src, dst, e);

    // ---- layer 1 ----
    k_gemm<<<gGemm, b256>>>(x, W1, d_h, n, nullptr, nullptr);
    k_agg<<<gAgg, b256>>>(d_h, b1, d_t, n);
    k_finalize<<<1, DD>>>(ga1, be1, inv_n);

    // ---- layer 2 (BN1+ReLU fused into GEMM2's X load) ----
    k_gemm<<<gGemm, b256>>>(d_t, W2, d_h, n, d_scale, d_shift);
    k_agg<<<gAgg, b256>>>(d_h, b2, d_t, n);
    k_finalize<<<1, DD>>>(ga2, be2, inv_n);

    // ---- epilogue ----
    k_bnfinal<<<gBn, b256>>>(out, x, n4);
}